// round 11
// baseline (speedup 1.0000x reference)
#include <cuda_runtime.h>
#include <cstddef>

#define KCODES 1024
#define DDIM   256
#define NPIX   65536
#define THREADS 256
#define MARGIN  7.5e-5f
#define CAND_SLACK 2e-4f

// ---- main kernel geometry ----
#define BPW 128      // pixels per block
#define TKW 128      // codes per register tile
#define ZW_OFF  0                        // 32768 floats
#define ENW_OFF 32768                    // 1024
#define AW_OFF  (32768 + 1024)           // 128
#define SMEMW_FLOATS (AW_OFF + 128)      // 34048 floats = 136,192 B

__device__ float g_enorm[KCODES];
__device__ float g_A[NPIX];
__device__ float g_bv[NPIX];
__device__ int   g_nflag;
__device__ int   g_flags[NPIX];
__device__ unsigned long long g_e2[DDIM * KCODES];   // e2[d][k] = {e,e} (2 MB)

#define FMA2(a, x, y) \
    asm("fma.rn.f32x2 %0, %1, %2, %0;" : "+l"(a) : "l"(x), "l"(y))
#define DUP2(d, s) \
    asm("mov.b64 %0, {%1,%1};" : "=l"(d) : "f"(s))

// ---------------------------------------------------------------------------
// Emulated reference row sum-of-squares (proven exact R7-R10).
// ---------------------------------------------------------------------------
__device__ __forceinline__ float sumsq_emul(const float* x, long stride) {
    float S[8];
#pragma unroll
    for (int l = 0; l < 8; l++) S[l] = 0.f;
    for (int t = 0; t < DDIM / 8; t++) {
#pragma unroll
        for (int l = 0; l < 8; l++) {
            float v = x[(long)(8 * t + l) * stride];
            S[l] = __fadd_rn(S[l], __fmul_rn(v, v));
        }
    }
    float m0 = __fadd_rn(S[0], S[4]);
    float m1 = __fadd_rn(S[1], S[5]);
    float m2 = __fadd_rn(S[2], S[6]);
    float m3 = __fadd_rn(S[3], S[7]);
    return __fadd_rn(__fadd_rn(m0, m1), __fadd_rn(m2, m3));
}

__global__ void reset_kernel() { if (threadIdx.x == 0) g_nflag = 0; }

__global__ void enorm_kernel(const float* __restrict__ emb) {
    int c = blockIdx.x * blockDim.x + threadIdx.x;
    if (c < KCODES) g_enorm[c] = sumsq_emul(emb + (size_t)c * DDIM, 1);
}

__global__ void anorm_kernel(const float* __restrict__ z) {
    int p = blockIdx.x * blockDim.x + threadIdx.x;
    if (p < NPIX) {
        const float* zp = z + (size_t)(p >> 12) * (DDIM * 4096) + (p & 4095);
        g_A[p] = sumsq_emul(zp, 4096);
    }
}

// build e2[d][k] = duplicated pair of emb[k][d]
__global__ void etrans_kernel(const float* __restrict__ emb) {
    int idx = blockIdx.x * blockDim.x + threadIdx.x;   // 0..262143
    int k = idx & 1023, d = idx >> 10;
    float v = emb[(size_t)k * DDIM + d];
    unsigned long long u;
    DUP2(u, v);
    g_e2[(size_t)d * KCODES + k] = u;
}

// ---------------------------------------------------------------------------
// Main pass: 128 px/block, 8 px x 8 codes per thread, packed f32x2.
// e streamed pre-duplicated from g_e2 (L2) — no e staging, no inner syncs.
// ---------------------------------------------------------------------------
__global__ __launch_bounds__(THREADS, 1)
void vq3(const float* __restrict__ z, float* __restrict__ out) {
    extern __shared__ float smem[];
    float* z_s  = smem + ZW_OFF;
    float* en_s = smem + ENW_OFF;
    float* A_s  = smem + AW_OFF;

    const int tid = threadIdx.x;
    const int tx  = tid & 15;    // 16 groups x 8 px  = 128 px
    const int ty  = tid >> 4;    // 16 groups x 8 cod = 128 codes/tile

    const int n0 = blockIdx.x * BPW;
    const float* zbase = z + (size_t)(n0 >> 12) * (DDIM * 4096) + (n0 & 4095);

    // ---- z tile [256][128], coalesced ----
#pragma unroll
    for (int it = 0; it < 32; it++) {
        int idx = it * THREADS + tid;
        int d = idx >> 5, c4 = (idx & 31) << 2;
        *(float4*)(z_s + d * BPW + c4) =
            *(const float4*)(zbase + (size_t)d * 4096 + c4);
    }
    for (int i = tid; i < KCODES; i += THREADS) en_s[i] = g_enorm[i];
    if (tid < BPW) A_s[tid] = g_A[n0 + tid];
    __syncthreads();

    float A8[8];
#pragma unroll
    for (int j = 0; j < 8; j++) A8[j] = A_s[tx * 8 + j];

    float bv[8], sv[8]; int bi[8];
#pragma unroll
    for (int j = 0; j < 8; j++) { bv[j] = 3.4e38f; sv[j] = 3.4e38f; bi[j] = 0; }

    const float* zrow = z_s + tx * 8;

    for (int k0 = 0; k0 < KCODES; k0 += TKW) {
        unsigned long long acc[4][8];
#pragma unroll
        for (int i = 0; i < 4; i++)
#pragma unroll
            for (int c = 0; c < 8; c++) acc[i][c] = 0ull;

        const unsigned long long* erow = g_e2 + k0 + ty * 8;

#pragma unroll 2
        for (int d = 0; d < DDIM; d++) {
            ulonglong2 za = *(const ulonglong2*)(zrow + (size_t)d * BPW);
            ulonglong2 zb = *(const ulonglong2*)(zrow + (size_t)d * BPW + 4);
            ulonglong2 p0 = *(const ulonglong2*)(erow + (size_t)d * KCODES);
            ulonglong2 p1 = *(const ulonglong2*)(erow + (size_t)d * KCODES + 2);
            ulonglong2 p2 = *(const ulonglong2*)(erow + (size_t)d * KCODES + 4);
            ulonglong2 p3 = *(const ulonglong2*)(erow + (size_t)d * KCODES + 6);
            unsigned long long zz[4] = {za.x, za.y, zb.x, zb.y};
            unsigned long long ed[8] = {p0.x, p0.y, p1.x, p1.y,
                                        p2.x, p2.y, p3.x, p3.y};
#pragma unroll
            for (int i = 0; i < 4; i++)
#pragma unroll
                for (int c = 0; c < 8; c++)
                    FMA2(acc[i][c], zz[i], ed[c]);
        }

        // epilogue: exact reference fp32 dist; ascending k, strict '<'
#pragma unroll
        for (int c = 0; c < 8; c++) {
            int k = k0 + ty * 8 + c;
            float en = en_s[k];
#pragma unroll
            for (int i = 0; i < 4; i++) {
                float lo = __uint_as_float((unsigned)(acc[i][c] & 0xffffffffull));
                float hi = __uint_as_float((unsigned)(acc[i][c] >> 32));
                float d0v = __fadd_rn(__fsub_rn(A8[2*i],   __fmul_rn(2.0f, lo)), en);
                float d1v = __fadd_rn(__fsub_rn(A8[2*i+1], __fmul_rn(2.0f, hi)), en);
                int j0 = 2 * i, j1 = 2 * i + 1;
                if (d0v < bv[j0]) { sv[j0] = bv[j0]; bv[j0] = d0v; bi[j0] = k; }
                else if (d0v < sv[j0]) sv[j0] = d0v;
                if (d1v < bv[j1]) { sv[j1] = bv[j1]; bv[j1] = d1v; bi[j1] = k; }
                else if (d1v < sv[j1]) sv[j1] = d1v;
            }
        }
    }

    // ---- cross-thread merge (16 ty contributors per pixel) ----
    __syncthreads();
    float* rv = z_s;                     // reuse: [128][17]
    int*   ri = (int*)(z_s + 2176);
    float* rs = z_s + 4352;
#pragma unroll
    for (int j = 0; j < 8; j++) {
        int p = tx * 8 + j;
        rv[p * 17 + ty] = bv[j];
        ri[p * 17 + ty] = bi[j];
        rs[p * 17 + ty] = sv[j];
    }
    __syncthreads();
    if (tid < BPW) {
        float b = rv[tid * 17]; int x0 = ri[tid * 17]; float s = rs[tid * 17];
#pragma unroll
        for (int t = 1; t < 16; t++) {
            float v = rv[tid * 17 + t]; int x = ri[tid * 17 + t];
            float s2 = rs[tid * 17 + t];
            if (v < b || (v == b && x < x0)) { s = fminf(b, s2); b = v; x0 = x; }
            else s = fminf(s, v);
        }
        out[n0 + tid]  = (float)x0;
        g_bv[n0 + tid] = b;
        if (__fsub_rn(s, b) < MARGIN) {
            int idx = atomicAdd(&g_nflag, 1);
            g_flags[idx] = n0 + tid;
        }
    }
}

// ---------------------------------------------------------------------------
// Fixup: screen candidates (fp32) then DF-exact dots only on candidates.
// Index tie-break makes candidate visit order irrelevant.
// ---------------------------------------------------------------------------
#define FPX 16
#define MAXC 32

__device__ __forceinline__ float df_dist(const float* zcol, const float* er,
                                         float A, float en) {
    float hi = 0.f, lo = 0.f;
    for (int d = 0; d < DDIM; d++) {
        float x = zcol[d * FPX], y = er[d];
        float pm = __fmul_rn(x, y);
        float e1 = fmaf(x, y, -pm);
        float t  = __fadd_rn(hi, pm);
        float v  = __fsub_rn(t, hi);
        float e2 = __fadd_rn(__fsub_rn(hi, __fsub_rn(t, v)), __fsub_rn(pm, v));
        hi = t;
        lo = __fadd_rn(lo, __fadd_rn(e1, e2));
    }
    float M = __fadd_rn(hi, lo);
    return __fadd_rn(__fsub_rn(A, __fmul_rn(2.0f, M)), en);
}

__global__ __launch_bounds__(THREADS)
void fixup3(const float* __restrict__ z, const float* __restrict__ emb,
            float* __restrict__ out) {
    __shared__ float z_s[DDIM * FPX];   // 16 KB, [d][px]
    __shared__ float en_s[KCODES];
    __shared__ float A_s[FPX], bv_s[FPX];
    __shared__ int   pl_s[FPX], ccnt[FPX];
    __shared__ int   cand[FPX][MAXC];

    const int tid = threadIdx.x;
    for (int i = tid; i < KCODES; i += THREADS) en_s[i] = g_enorm[i];

    for (int base = blockIdx.x * FPX; base < g_nflag; base += gridDim.x * FPX) {
        int nhere = g_nflag - base; if (nhere > FPX) nhere = FPX;
        __syncthreads();
        if (tid < FPX) {
            int p = g_flags[base + (tid < nhere ? tid : 0)];
            pl_s[tid] = p;
            A_s[tid]  = g_A[p];
            bv_s[tid] = g_bv[p];
            ccnt[tid] = 0;
        }
        __syncthreads();
        for (int i = tid; i < DDIM * FPX; i += THREADS) {
            int d = i >> 4, q = i & 15;
            int p = pl_s[q];
            z_s[i] = z[(size_t)(p >> 12) * (DDIM * 4096)
                       + (size_t)d * 4096 + (p & 4095)];
        }
        __syncthreads();

        // screening: px = tid&15, two interleaved code chains per iteration
        {
            int px = tid & 15, kg = tid >> 4;
            float A = A_s[px], thr = __fadd_rn(bv_s[px], CAND_SLACK);
            const float* zcol = z_s + px;
            for (int j = 0; j < 32; j++) {
                int k1 = kg + 16 * j;
                int k2 = k1 + 512;
                const float* e1r = emb + (size_t)k1 * DDIM;
                const float* e2r = emb + (size_t)k2 * DDIM;
                float a1 = 0.f, a2 = 0.f;
#pragma unroll 8
                for (int d = 0; d < DDIM; d++) {
                    float zv = zcol[d * FPX];
                    a1 = fmaf(zv, e1r[d], a1);
                    a2 = fmaf(zv, e2r[d], a2);
                }
                float d1 = __fadd_rn(__fsub_rn(A, __fmul_rn(2.0f, a1)), en_s[k1]);
                float d2 = __fadd_rn(__fsub_rn(A, __fmul_rn(2.0f, a2)), en_s[k2]);
                if (d1 < thr) {
                    int s = atomicAdd(&ccnt[px], 1);
                    if (s < MAXC) cand[px][s] = k1;
                }
                if (d2 < thr) {
                    int s = atomicAdd(&ccnt[px], 1);
                    if (s < MAXC) cand[px][s] = k2;
                }
            }
        }
        __syncthreads();

        // DF phase: warp w handles px w, w+8
        {
            int warp = tid >> 5, lane = tid & 31;
            for (int pp = warp; pp < FPX; pp += 8) {
                int cnt = ccnt[pp];
                const float* zcol = z_s + pp;
                float A = A_s[pp];
                float bb = 3.4e38f; int bk = KCODES;
                if (cnt <= MAXC) {
                    if (lane < cnt) {
                        int k = cand[pp][lane];
                        bb = df_dist(zcol, emb + (size_t)k * DDIM, A, en_s[k]);
                        bk = k;
                    }
                } else {            // overflow fallback: all codes (never expected)
                    for (int k = lane; k < KCODES; k += 32) {
                        float dv = df_dist(zcol, emb + (size_t)k * DDIM, A, en_s[k]);
                        if (dv < bb || (dv == bb && k < bk)) { bb = dv; bk = k; }
                    }
                }
#pragma unroll
                for (int off = 16; off; off >>= 1) {
                    float ov = __shfl_xor_sync(0xffffffffu, bb, off);
                    int   ok = __shfl_xor_sync(0xffffffffu, bk, off);
                    if (ov < bb || (ov == bb && ok < bk)) { bb = ov; bk = ok; }
                }
                if (lane == 0 && pp < nhere) out[pl_s[pp]] = (float)bk;
            }
        }
    }
}

// ---------------------------------------------------------------------------
extern "C" void kernel_launch(void* const* d_in, const int* in_sizes, int n_in,
                              void* d_out, int out_size) {
    const float* z   = nullptr;
    const float* emb = nullptr;
    for (int i = 0; i < n_in; i++) {
        long s = (long)in_sizes[i];
        if (s == 16777216L || s == 67108864L)   z   = (const float*)d_in[i];
        else if (s == 262144L || s == 1048576L) emb = (const float*)d_in[i];
    }
    if (!z)   z   = (const float*)d_in[0];
    if (!emb) emb = (const float*)d_in[n_in > 1 ? 1 : 0];
    float* out = (float*)d_out;

    reset_kernel<<<1, 32>>>();
    enorm_kernel<<<32, 32>>>(emb);
    anorm_kernel<<<NPIX / 128, 128>>>(z);
    etrans_kernel<<<KCODES * DDIM / 256, 256>>>(emb);

    size_t smw = (size_t)SMEMW_FLOATS * sizeof(float);
    cudaFuncSetAttribute(vq3, cudaFuncAttributeMaxDynamicSharedMemorySize,
                         (int)smw);
    vq3<<<NPIX / BPW, THREADS, smw>>>(z, out);
    fixup3<<<256, THREADS>>>(z, emb, out);
}

// round 12
// speedup vs baseline: 1.3036x; 1.3036x over previous
#include <cuda_runtime.h>
#include <cstddef>

#define KCODES 1024
#define DDIM   256
#define NPIX   65536
#define THREADS 256
#define MARGIN  7.5e-5f
#define CAND_SLACK 2e-4f

// ---- main kernel geometry ----
#define BPW 128      // pixels per block
#define TKW 128      // codes per tile
#define DCW 32       // d per chunk
#define SEK 132      // e2 row stride in u64 (128 codes + pad)
#define CHUNK_U64 (DCW * SEK)            // 4224 u64 per buffer

// smem: z (32768 f) | e2 2 buffers (16896 f) | en (1024 f) | A (128 f)
#define ZW_OFF   0
#define E2_OFF   32768                   // as float index; cast to u64*
#define ENW_OFF  (32768 + 16896)
#define AW_OFF   (ENW_OFF + 1024)
#define SMEMW_FLOATS (AW_OFF + 128)      // 50816 floats = 203,264 B

__device__ float g_enorm[KCODES];
__device__ float g_A[NPIX];
__device__ float g_bv[NPIX];
__device__ int   g_nflag;
__device__ int   g_flags[NPIX];

#define FMA2(a, x, y) \
    asm("fma.rn.f32x2 %0, %1, %2, %0;" : "+l"(a) : "l"(x), "l"(y))
#define DUP2(d, s) \
    asm("mov.b64 %0, {%1,%1};" : "=l"(d) : "f"(s))

// ---------------------------------------------------------------------------
// Emulated reference row sum-of-squares (proven exact R7-R11).
// ---------------------------------------------------------------------------
__device__ __forceinline__ float sumsq_emul(const float* x, long stride) {
    float S[8];
#pragma unroll
    for (int l = 0; l < 8; l++) S[l] = 0.f;
    for (int t = 0; t < DDIM / 8; t++) {
#pragma unroll
        for (int l = 0; l < 8; l++) {
            float v = x[(long)(8 * t + l) * stride];
            S[l] = __fadd_rn(S[l], __fmul_rn(v, v));
        }
    }
    float m0 = __fadd_rn(S[0], S[4]);
    float m1 = __fadd_rn(S[1], S[5]);
    float m2 = __fadd_rn(S[2], S[6]);
    float m3 = __fadd_rn(S[3], S[7]);
    return __fadd_rn(__fadd_rn(m0, m1), __fadd_rn(m2, m3));
}

__global__ void reset_kernel() { if (threadIdx.x == 0) g_nflag = 0; }

__global__ void enorm_kernel(const float* __restrict__ emb) {
    int c = blockIdx.x * blockDim.x + threadIdx.x;
    if (c < KCODES) g_enorm[c] = sumsq_emul(emb + (size_t)c * DDIM, 1);
}

__global__ void anorm_kernel(const float* __restrict__ z) {
    int p = blockIdx.x * blockDim.x + threadIdx.x;
    if (p < NPIX) {
        const float* zp = z + (size_t)(p >> 12) * (DDIM * 4096) + (p & 4095);
        g_A[p] = sumsq_emul(zp, 4096);
    }
}

// ---------------------------------------------------------------------------
// Main pass: 128 px/block, 8 px x 8 codes/thread, packed f32x2.
// e staged into smem PRE-DUPLICATED as u64 {e,e}; double-buffered staging
// with LDG-prefetch into registers -> one sync per chunk, no DUPs in hot loop.
// ---------------------------------------------------------------------------
__global__ __launch_bounds__(THREADS, 1)
void vq4(const float* __restrict__ z, const float* __restrict__ emb,
         float* __restrict__ out) {
    extern __shared__ float smem[];
    float* z_s  = smem + ZW_OFF;
    unsigned long long* e2 = (unsigned long long*)(smem + E2_OFF);
    float* en_s = smem + ENW_OFF;
    float* A_s  = smem + AW_OFF;

    const int tid = threadIdx.x;
    const int tx  = tid & 15;    // 16 groups x 8 px  = 128 px
    const int ty  = tid >> 4;    // 16 groups x 8 cod = 128 codes/tile

    const int n0 = blockIdx.x * BPW;
    const float* zbase = z + (size_t)(n0 >> 12) * (DDIM * 4096) + (n0 & 4095);

    // ---- z tile [256][128], coalesced ----
#pragma unroll
    for (int it = 0; it < 32; it++) {
        int idx = it * THREADS + tid;
        int d = idx >> 5, c4 = (idx & 31) << 2;
        *(float4*)(z_s + d * BPW + c4) =
            *(const float4*)(zbase + (size_t)d * 4096 + c4);
    }
    for (int i = tid; i < KCODES; i += THREADS) en_s[i] = g_enorm[i];
    if (tid < BPW) A_s[tid] = g_A[n0 + tid];
    __syncthreads();

    float A8[8];
#pragma unroll
    for (int j = 0; j < 8; j++) A8[j] = A_s[tx * 8 + j];

    float bv[8], sv[8]; int bi[8];
#pragma unroll
    for (int j = 0; j < 8; j++) { bv[j] = 3.4e38f; sv[j] = 3.4e38f; bi[j] = 0; }

    // staging identity for this thread: covers 16 d-values of one code
    const int s_code = tid >> 1;         // 0..127
    const int s_q    = tid & 1;          // 0 or 1 (d half)
    const float* zrow = z_s + tx * 8;

    for (int k0 = 0; k0 < KCODES; k0 += TKW) {
        unsigned long long acc[4][8];
#pragma unroll
        for (int i = 0; i < 4; i++)
#pragma unroll
            for (int c = 0; c < 8; c++) acc[i][c] = 0ull;

        const float* erow_base = emb + (size_t)(k0 + s_code) * DDIM + s_q * 16;

        // prologue: load + store chunk 0 into buffer 0
        float4 st0, st1, st2, st3;
        {
            const float* erow = erow_base;           // d0 = 0
            st0 = *(const float4*)(erow + 0);
            st1 = *(const float4*)(erow + 4);
            st2 = *(const float4*)(erow + 8);
            st3 = *(const float4*)(erow + 12);
            unsigned long long* dst = e2 + (s_q * 16) * SEK + s_code;
            float f[16] = {st0.x, st0.y, st0.z, st0.w, st1.x, st1.y, st1.z, st1.w,
                           st2.x, st2.y, st2.z, st2.w, st3.x, st3.y, st3.z, st3.w};
#pragma unroll
            for (int j = 0; j < 16; j++) {
                unsigned long long u; DUP2(u, f[j]);
                dst[j * SEK] = u;
            }
        }
        __syncthreads();

        for (int ch = 0; ch < DDIM / DCW; ch++) {
            // prefetch next chunk's e into registers (latency hidden by compute)
            if (ch < DDIM / DCW - 1) {
                const float* erow = erow_base + (ch + 1) * DCW;
                st0 = *(const float4*)(erow + 0);
                st1 = *(const float4*)(erow + 4);
                st2 = *(const float4*)(erow + 8);
                st3 = *(const float4*)(erow + 12);
            }

            // compute current chunk from buffer ch&1
            const unsigned long long* ebase = e2 + (ch & 1) * CHUNK_U64 + ty * 8;
            const int dg = ch * DCW;
#pragma unroll 4
            for (int d = 0; d < DCW; d++) {
                ulonglong2 za = *(const ulonglong2*)(zrow + (size_t)(dg + d) * BPW);
                ulonglong2 zb = *(const ulonglong2*)(zrow + (size_t)(dg + d) * BPW + 4);
                ulonglong2 p0 = *(const ulonglong2*)(ebase + (size_t)d * SEK);
                ulonglong2 p1 = *(const ulonglong2*)(ebase + (size_t)d * SEK + 2);
                ulonglong2 p2 = *(const ulonglong2*)(ebase + (size_t)d * SEK + 4);
                ulonglong2 p3 = *(const ulonglong2*)(ebase + (size_t)d * SEK + 6);
                unsigned long long zz[4] = {za.x, za.y, zb.x, zb.y};
                unsigned long long ed[8] = {p0.x, p0.y, p1.x, p1.y,
                                            p2.x, p2.y, p3.x, p3.y};
#pragma unroll
                for (int i = 0; i < 4; i++)
#pragma unroll
                    for (int c = 0; c < 8; c++)
                        FMA2(acc[i][c], zz[i], ed[c]);
            }

            // store prefetched chunk into the idle buffer, then one sync
            if (ch < DDIM / DCW - 1) {
                unsigned long long* dst =
                    e2 + ((ch + 1) & 1) * CHUNK_U64 + (s_q * 16) * SEK + s_code;
                float f[16] = {st0.x, st0.y, st0.z, st0.w, st1.x, st1.y, st1.z, st1.w,
                               st2.x, st2.y, st2.z, st2.w, st3.x, st3.y, st3.z, st3.w};
#pragma unroll
                for (int j = 0; j < 16; j++) {
                    unsigned long long u; DUP2(u, f[j]);
                    dst[j * SEK] = u;
                }
            }
            __syncthreads();
        }

        // epilogue: exact reference fp32 dist; ascending k, strict '<'
#pragma unroll
        for (int c = 0; c < 8; c++) {
            int k = k0 + ty * 8 + c;
            float en = en_s[k];
#pragma unroll
            for (int i = 0; i < 4; i++) {
                float lo = __uint_as_float((unsigned)(acc[i][c] & 0xffffffffull));
                float hi = __uint_as_float((unsigned)(acc[i][c] >> 32));
                float d0v = __fadd_rn(__fsub_rn(A8[2*i],   __fmul_rn(2.0f, lo)), en);
                float d1v = __fadd_rn(__fsub_rn(A8[2*i+1], __fmul_rn(2.0f, hi)), en);
                int j0 = 2 * i, j1 = 2 * i + 1;
                if (d0v < bv[j0]) { sv[j0] = bv[j0]; bv[j0] = d0v; bi[j0] = k; }
                else if (d0v < sv[j0]) sv[j0] = d0v;
                if (d1v < bv[j1]) { sv[j1] = bv[j1]; bv[j1] = d1v; bi[j1] = k; }
                else if (d1v < sv[j1]) sv[j1] = d1v;
            }
        }
    }

    // ---- cross-thread merge (16 ty contributors per pixel) ----
    __syncthreads();
    float* rv = z_s;                     // reuse: [128][17]
    int*   ri = (int*)(z_s + 2176);
    float* rs = z_s + 4352;
#pragma unroll
    for (int j = 0; j < 8; j++) {
        int p = tx * 8 + j;
        rv[p * 17 + ty] = bv[j];
        ri[p * 17 + ty] = bi[j];
        rs[p * 17 + ty] = sv[j];
    }
    __syncthreads();
    if (tid < BPW) {
        float b = rv[tid * 17]; int x0 = ri[tid * 17]; float s = rs[tid * 17];
#pragma unroll
        for (int t = 1; t < 16; t++) {
            float v = rv[tid * 17 + t]; int x = ri[tid * 17 + t];
            float s2 = rs[tid * 17 + t];
            if (v < b || (v == b && x < x0)) { s = fminf(b, s2); b = v; x0 = x; }
            else s = fminf(s, v);
        }
        out[n0 + tid]  = (float)x0;
        g_bv[n0 + tid] = b;
        if (__fsub_rn(s, b) < MARGIN) {
            int idx = atomicAdd(&g_nflag, 1);
            g_flags[idx] = n0 + tid;
        }
    }
}

// ---------------------------------------------------------------------------
// Fixup: fp32 candidate screening, then DF-exact dots on candidates only
// (validated in R11; index tie-break makes collection order irrelevant).
// ---------------------------------------------------------------------------
#define FPX 16
#define MAXC 32

__device__ __forceinline__ float df_dist(const float* zcol, const float* er,
                                         float A, float en) {
    float hi = 0.f, lo = 0.f;
    for (int d = 0; d < DDIM; d++) {
        float x = zcol[d * FPX], y = er[d];
        float pm = __fmul_rn(x, y);
        float e1 = fmaf(x, y, -pm);
        float t  = __fadd_rn(hi, pm);
        float v  = __fsub_rn(t, hi);
        float e2 = __fadd_rn(__fsub_rn(hi, __fsub_rn(t, v)), __fsub_rn(pm, v));
        hi = t;
        lo = __fadd_rn(lo, __fadd_rn(e1, e2));
    }
    float M = __fadd_rn(hi, lo);
    return __fadd_rn(__fsub_rn(A, __fmul_rn(2.0f, M)), en);
}

__global__ __launch_bounds__(THREADS)
void fixup3(const float* __restrict__ z, const float* __restrict__ emb,
            float* __restrict__ out) {
    __shared__ float z_s[DDIM * FPX];
    __shared__ float en_s[KCODES];
    __shared__ float A_s[FPX], bv_s[FPX];
    __shared__ int   pl_s[FPX], ccnt[FPX];
    __shared__ int   cand[FPX][MAXC];

    const int tid = threadIdx.x;
    for (int i = tid; i < KCODES; i += THREADS) en_s[i] = g_enorm[i];

    for (int base = blockIdx.x * FPX; base < g_nflag; base += gridDim.x * FPX) {
        int nhere = g_nflag - base; if (nhere > FPX) nhere = FPX;
        __syncthreads();
        if (tid < FPX) {
            int p = g_flags[base + (tid < nhere ? tid : 0)];
            pl_s[tid] = p;
            A_s[tid]  = g_A[p];
            bv_s[tid] = g_bv[p];
            ccnt[tid] = 0;
        }
        __syncthreads();
        for (int i = tid; i < DDIM * FPX; i += THREADS) {
            int d = i >> 4, q = i & 15;
            int p = pl_s[q];
            z_s[i] = z[(size_t)(p >> 12) * (DDIM * 4096)
                       + (size_t)d * 4096 + (p & 4095)];
        }
        __syncthreads();

        {   // screening
            int px = tid & 15, kg = tid >> 4;
            float A = A_s[px], thr = __fadd_rn(bv_s[px], CAND_SLACK);
            const float* zcol = z_s + px;
            for (int j = 0; j < 32; j++) {
                int k1 = kg + 16 * j;
                int k2 = k1 + 512;
                const float* e1r = emb + (size_t)k1 * DDIM;
                const float* e2r = emb + (size_t)k2 * DDIM;
                float a1 = 0.f, a2 = 0.f;
#pragma unroll 8
                for (int d = 0; d < DDIM; d++) {
                    float zv = zcol[d * FPX];
                    a1 = fmaf(zv, e1r[d], a1);
                    a2 = fmaf(zv, e2r[d], a2);
                }
                float d1 = __fadd_rn(__fsub_rn(A, __fmul_rn(2.0f, a1)), en_s[k1]);
                float d2 = __fadd_rn(__fsub_rn(A, __fmul_rn(2.0f, a2)), en_s[k2]);
                if (d1 < thr) {
                    int s = atomicAdd(&ccnt[px], 1);
                    if (s < MAXC) cand[px][s] = k1;
                }
                if (d2 < thr) {
                    int s = atomicAdd(&ccnt[px], 1);
                    if (s < MAXC) cand[px][s] = k2;
                }
            }
        }
        __syncthreads();

        {   // DF phase: warp w handles px w, w+8
            int warp = tid >> 5, lane = tid & 31;
            for (int pp = warp; pp < FPX; pp += 8) {
                int cnt = ccnt[pp];
                const float* zcol = z_s + pp;
                float A = A_s[pp];
                float bb = 3.4e38f; int bk = KCODES;
                if (cnt <= MAXC) {
                    if (lane < cnt) {
                        int k = cand[pp][lane];
                        bb = df_dist(zcol, emb + (size_t)k * DDIM, A, en_s[k]);
                        bk = k;
                    }
                } else {
                    for (int k = lane; k < KCODES; k += 32) {
                        float dv = df_dist(zcol, emb + (size_t)k * DDIM, A, en_s[k]);
                        if (dv < bb || (dv == bb && k < bk)) { bb = dv; bk = k; }
                    }
                }
#pragma unroll
                for (int off = 16; off; off >>= 1) {
                    float ov = __shfl_xor_sync(0xffffffffu, bb, off);
                    int   ok = __shfl_xor_sync(0xffffffffu, bk, off);
                    if (ov < bb || (ov == bb && ok < bk)) { bb = ov; bk = ok; }
                }
                if (lane == 0 && pp < nhere) out[pl_s[pp]] = (float)bk;
            }
        }
    }
}

// ---------------------------------------------------------------------------
extern "C" void kernel_launch(void* const* d_in, const int* in_sizes, int n_in,
                              void* d_out, int out_size) {
    const float* z   = nullptr;
    const float* emb = nullptr;
    for (int i = 0; i < n_in; i++) {
        long s = (long)in_sizes[i];
        if (s == 16777216L || s == 67108864L)   z   = (const float*)d_in[i];
        else if (s == 262144L || s == 1048576L) emb = (const float*)d_in[i];
    }
    if (!z)   z   = (const float*)d_in[0];
    if (!emb) emb = (const float*)d_in[n_in > 1 ? 1 : 0];
    float* out = (float*)d_out;

    reset_kernel<<<1, 32>>>();
    enorm_kernel<<<32, 32>>>(emb);
    anorm_kernel<<<NPIX / 128, 128>>>(z);

    size_t smw = (size_t)SMEMW_FLOATS * sizeof(float);
    cudaFuncSetAttribute(vq4, cudaFuncAttributeMaxDynamicSharedMemorySize,
                         (int)smw);
    vq4<<<NPIX / BPW, THREADS, smw>>>(z, emb, out);
    fixup3<<<256, THREADS>>>(z, emb, out);
}

// round 13
// speedup vs baseline: 1.3148x; 1.0087x over previous
#include <cuda_runtime.h>
#include <cstddef>

#define KCODES 1024
#define DDIM   256
#define NPIX   65536
#define THREADS 512
#define MARGIN  7.5e-5f
#define CAND_SLACK 2e-4f

// ---- main kernel geometry ----
#define BPW 128      // pixels per block
#define TKW 128      // codes per tile
#define DCW 32       // d per chunk
#define SEK 132      // e2 row stride in u64
#define CHUNK_U64 (DCW * SEK)

// smem: z (32768 f) | e2 2 buffers (16896 f) | en (1024 f) | A (128 f)
#define ZW_OFF   0
#define E2_OFF   32768
#define ENW_OFF  (32768 + 16896)
#define AW_OFF   (ENW_OFF + 1024)
#define SMEMW_FLOATS (AW_OFF + 128)      // 50816 floats = 203,264 B

__device__ float g_enorm[KCODES];
__device__ float g_A[NPIX];
__device__ float g_bv[NPIX];
__device__ int   g_nflag;
__device__ int   g_flags[NPIX];

#define FMA2(a, x, y) \
    asm("fma.rn.f32x2 %0, %1, %2, %0;" : "+l"(a) : "l"(x), "l"(y))
#define DUP2(d, s) \
    asm("mov.b64 %0, {%1,%1};" : "=l"(d) : "f"(s))

// ---------------------------------------------------------------------------
// Emulated reference row sum-of-squares (proven exact R7-R12).
// ---------------------------------------------------------------------------
__device__ __forceinline__ float sumsq_emul(const float* x, long stride) {
    float S[8];
#pragma unroll
    for (int l = 0; l < 8; l++) S[l] = 0.f;
    for (int t = 0; t < DDIM / 8; t++) {
#pragma unroll
        for (int l = 0; l < 8; l++) {
            float v = x[(long)(8 * t + l) * stride];
            S[l] = __fadd_rn(S[l], __fmul_rn(v, v));
        }
    }
    float m0 = __fadd_rn(S[0], S[4]);
    float m1 = __fadd_rn(S[1], S[5]);
    float m2 = __fadd_rn(S[2], S[6]);
    float m3 = __fadd_rn(S[3], S[7]);
    return __fadd_rn(__fadd_rn(m0, m1), __fadd_rn(m2, m3));
}

__global__ void reset_kernel() { if (threadIdx.x == 0) g_nflag = 0; }

__global__ void enorm_kernel(const float* __restrict__ emb) {
    int c = blockIdx.x * blockDim.x + threadIdx.x;
    if (c < KCODES) g_enorm[c] = sumsq_emul(emb + (size_t)c * DDIM, 1);
}

__global__ void anorm_kernel(const float* __restrict__ z) {
    int p = blockIdx.x * blockDim.x + threadIdx.x;
    if (p < NPIX) {
        const float* zp = z + (size_t)(p >> 12) * (DDIM * 4096) + (p & 4095);
        g_A[p] = sumsq_emul(zp, 4096);
    }
}

// ---------------------------------------------------------------------------
// Main pass: 512 threads, 128 px/block. Warp = 32 px x 32 codes
// (thread = 4 px x 8 codes). z LDS conflict-free 1-wf, e broadcast.
// Double-buffered pre-duplicated e2 staging (one sync per chunk).
// ---------------------------------------------------------------------------
__global__ __launch_bounds__(THREADS, 1)
void vq5(const float* __restrict__ z, const float* __restrict__ emb,
         float* __restrict__ out) {
    extern __shared__ float smem[];
    float* z_s  = smem + ZW_OFF;
    unsigned long long* e2 = (unsigned long long*)(smem + E2_OFF);
    float* en_s = smem + ENW_OFF;
    float* A_s  = smem + AW_OFF;

    const int tid  = threadIdx.x;
    const int lane = tid & 31;
    const int w    = tid >> 5;          // 16 warps
    const int pxg  = lane & 7;          // 8 px-groups
    const int cg   = lane >> 3;         // 4 code-groups
    const int band = w & 3;             // 4 px-bands of 32
    const int ccl  = w >> 2;            // 4 code-clusters of 32
    const int px0  = band * 32 + pxg * 4;        // this thread's 4 pixels
    const int cofs = ccl * 32 + cg * 8;          // 8 codes within tile

    const int n0 = blockIdx.x * BPW;
    const float* zbase = z + (size_t)(n0 >> 12) * (DDIM * 4096) + (n0 & 4095);

    // ---- z tile [256][128], coalesced ----
#pragma unroll
    for (int it = 0; it < 16; it++) {
        int idx = it * THREADS + tid;            // 8192 float4 slots
        int d = idx >> 5, c4 = (idx & 31) << 2;
        *(float4*)(z_s + d * BPW + c4) =
            *(const float4*)(zbase + (size_t)d * 4096 + c4);
    }
    for (int i = tid; i < KCODES; i += THREADS) en_s[i] = g_enorm[i];
    if (tid < BPW) A_s[tid] = g_A[n0 + tid];
    __syncthreads();

    float A4[4];
#pragma unroll
    for (int j = 0; j < 4; j++) A4[j] = A_s[px0 + j];

    float bv[4], sv[4]; int bi[4];
#pragma unroll
    for (int j = 0; j < 4; j++) { bv[j] = 3.4e38f; sv[j] = 3.4e38f; bi[j] = 0; }

    // staging identity: thread covers 8 d-rows of one code
    const int s_code = tid >> 2;        // 0..127
    const int s_q    = tid & 3;         // d-rows s_q*8 .. +7

    for (int k0 = 0; k0 < KCODES; k0 += TKW) {
        unsigned long long acc[2][8];   // 2 px-pairs x 8 codes
#pragma unroll
        for (int i = 0; i < 2; i++)
#pragma unroll
            for (int c = 0; c < 8; c++) acc[i][c] = 0ull;

        const float* erow_base = emb + (size_t)(k0 + s_code) * DDIM + s_q * 8;

        // prologue: load + dup-store chunk 0 into buffer 0
        float4 st0, st1;
        {
            st0 = *(const float4*)(erow_base + 0);
            st1 = *(const float4*)(erow_base + 4);
            unsigned long long* dst = e2 + (s_q * 8) * SEK + s_code;
            float f[8] = {st0.x, st0.y, st0.z, st0.w,
                          st1.x, st1.y, st1.z, st1.w};
#pragma unroll
            for (int j = 0; j < 8; j++) {
                unsigned long long u; DUP2(u, f[j]);
                dst[j * SEK] = u;
            }
        }
        __syncthreads();

        for (int ch = 0; ch < DDIM / DCW; ch++) {
            if (ch < DDIM / DCW - 1) {           // prefetch next chunk
                const float* erow = erow_base + (ch + 1) * DCW;
                st0 = *(const float4*)(erow + 0);
                st1 = *(const float4*)(erow + 4);
            }

            const unsigned long long* ebase =
                e2 + (ch & 1) * CHUNK_U64 + cofs;
            const int dg = ch * DCW;
#pragma unroll 4
            for (int d = 0; d < DCW; d++) {
                ulonglong2 zz = *(const ulonglong2*)(z_s + (size_t)(dg + d) * BPW + px0);
                ulonglong2 p0 = *(const ulonglong2*)(ebase + (size_t)d * SEK);
                ulonglong2 p1 = *(const ulonglong2*)(ebase + (size_t)d * SEK + 2);
                ulonglong2 p2 = *(const ulonglong2*)(ebase + (size_t)d * SEK + 4);
                ulonglong2 p3 = *(const ulonglong2*)(ebase + (size_t)d * SEK + 6);
                unsigned long long ed[8] = {p0.x, p0.y, p1.x, p1.y,
                                            p2.x, p2.y, p3.x, p3.y};
#pragma unroll
                for (int c = 0; c < 8; c++) FMA2(acc[0][c], zz.x, ed[c]);
#pragma unroll
                for (int c = 0; c < 8; c++) FMA2(acc[1][c], zz.y, ed[c]);
            }

            if (ch < DDIM / DCW - 1) {           // store prefetched chunk
                unsigned long long* dst =
                    e2 + ((ch + 1) & 1) * CHUNK_U64 + (s_q * 8) * SEK + s_code;
                float f[8] = {st0.x, st0.y, st0.z, st0.w,
                              st1.x, st1.y, st1.z, st1.w};
#pragma unroll
                for (int j = 0; j < 8; j++) {
                    unsigned long long u; DUP2(u, f[j]);
                    dst[j * SEK] = u;
                }
            }
            __syncthreads();
        }

        // epilogue: exact reference fp32 dist; ascending k, strict '<'
#pragma unroll
        for (int c = 0; c < 8; c++) {
            int k = k0 + cofs + c;
            float en = en_s[k];
#pragma unroll
            for (int i = 0; i < 2; i++) {
                float lo = __uint_as_float((unsigned)(acc[i][c] & 0xffffffffull));
                float hi = __uint_as_float((unsigned)(acc[i][c] >> 32));
                float d0v = __fadd_rn(__fsub_rn(A4[2*i],   __fmul_rn(2.0f, lo)), en);
                float d1v = __fadd_rn(__fsub_rn(A4[2*i+1], __fmul_rn(2.0f, hi)), en);
                int j0 = 2 * i, j1 = 2 * i + 1;
                if (d0v < bv[j0]) { sv[j0] = bv[j0]; bv[j0] = d0v; bi[j0] = k; }
                else if (d0v < sv[j0]) sv[j0] = d0v;
                if (d1v < bv[j1]) { sv[j1] = bv[j1]; bv[j1] = d1v; bi[j1] = k; }
                else if (d1v < sv[j1]) sv[j1] = d1v;
            }
        }
    }

    // ---- cross-thread merge: 16 contributors (ccl x cg) per pixel ----
    __syncthreads();
    float* rv = z_s;                     // reuse: [128][17]
    int*   ri = (int*)(z_s + 2176);
    float* rs = z_s + 4352;
    const int slot = ccl * 4 + cg;       // 0..15
#pragma unroll
    for (int j = 0; j < 4; j++) {
        int p = px0 + j;
        rv[p * 17 + slot] = bv[j];
        ri[p * 17 + slot] = bi[j];
        rs[p * 17 + slot] = sv[j];
    }
    __syncthreads();
    if (tid < BPW) {
        float b = rv[tid * 17]; int x0 = ri[tid * 17]; float s = rs[tid * 17];
#pragma unroll
        for (int t = 1; t < 16; t++) {
            float v = rv[tid * 17 + t]; int x = ri[tid * 17 + t];
            float s2 = rs[tid * 17 + t];
            if (v < b || (v == b && x < x0)) { s = fminf(b, s2); b = v; x0 = x; }
            else s = fminf(s, v);
        }
        out[n0 + tid]  = (float)x0;
        g_bv[n0 + tid] = b;
        if (__fsub_rn(s, b) < MARGIN) {
            int idx = atomicAdd(&g_nflag, 1);
            g_flags[idx] = n0 + tid;
        }
    }
}

// ---------------------------------------------------------------------------
// Fixup: fp32 candidate screening, then DF-exact dots on candidates only
// (validated R11/R12; index tie-break makes collection order irrelevant).
// ---------------------------------------------------------------------------
#define FTH 256
#define FPX 16
#define MAXC 32

__device__ __forceinline__ float df_dist(const float* zcol, const float* er,
                                         float A, float en) {
    float hi = 0.f, lo = 0.f;
    for (int d = 0; d < DDIM; d++) {
        float x = zcol[d * FPX], y = er[d];
        float pm = __fmul_rn(x, y);
        float e1 = fmaf(x, y, -pm);
        float t  = __fadd_rn(hi, pm);
        float v  = __fsub_rn(t, hi);
        float e2 = __fadd_rn(__fsub_rn(hi, __fsub_rn(t, v)), __fsub_rn(pm, v));
        hi = t;
        lo = __fadd_rn(lo, __fadd_rn(e1, e2));
    }
    float M = __fadd_rn(hi, lo);
    return __fadd_rn(__fsub_rn(A, __fmul_rn(2.0f, M)), en);
}

__global__ __launch_bounds__(FTH)
void fixup3(const float* __restrict__ z, const float* __restrict__ emb,
            float* __restrict__ out) {
    __shared__ float z_s[DDIM * FPX];
    __shared__ float en_s[KCODES];
    __shared__ float A_s[FPX], bv_s[FPX];
    __shared__ int   pl_s[FPX], ccnt[FPX];
    __shared__ int   cand[FPX][MAXC];

    const int tid = threadIdx.x;
    for (int i = tid; i < KCODES; i += FTH) en_s[i] = g_enorm[i];

    for (int base = blockIdx.x * FPX; base < g_nflag; base += gridDim.x * FPX) {
        int nhere = g_nflag - base; if (nhere > FPX) nhere = FPX;
        __syncthreads();
        if (tid < FPX) {
            int p = g_flags[base + (tid < nhere ? tid : 0)];
            pl_s[tid] = p;
            A_s[tid]  = g_A[p];
            bv_s[tid] = g_bv[p];
            ccnt[tid] = 0;
        }
        __syncthreads();
        for (int i = tid; i < DDIM * FPX; i += FTH) {
            int d = i >> 4, q = i & 15;
            int p = pl_s[q];
            z_s[i] = z[(size_t)(p >> 12) * (DDIM * 4096)
                       + (size_t)d * 4096 + (p & 4095)];
        }
        __syncthreads();

        {   // screening
            int px = tid & 15, kg = tid >> 4;
            float A = A_s[px], thr = __fadd_rn(bv_s[px], CAND_SLACK);
            const float* zcol = z_s + px;
            for (int j = 0; j < 32; j++) {
                int k1 = kg + 16 * j;
                int k2 = k1 + 512;
                const float* e1r = emb + (size_t)k1 * DDIM;
                const float* e2r = emb + (size_t)k2 * DDIM;
                float a1 = 0.f, a2 = 0.f;
#pragma unroll 8
                for (int d = 0; d < DDIM; d++) {
                    float zv = zcol[d * FPX];
                    a1 = fmaf(zv, e1r[d], a1);
                    a2 = fmaf(zv, e2r[d], a2);
                }
                float d1 = __fadd_rn(__fsub_rn(A, __fmul_rn(2.0f, a1)), en_s[k1]);
                float d2 = __fadd_rn(__fsub_rn(A, __fmul_rn(2.0f, a2)), en_s[k2]);
                if (d1 < thr) {
                    int s = atomicAdd(&ccnt[px], 1);
                    if (s < MAXC) cand[px][s] = k1;
                }
                if (d2 < thr) {
                    int s = atomicAdd(&ccnt[px], 1);
                    if (s < MAXC) cand[px][s] = k2;
                }
            }
        }
        __syncthreads();

        {   // DF phase: warp w handles px w, w+8
            int warp = tid >> 5, lane = tid & 31;
            for (int pp = warp; pp < FPX; pp += 8) {
                int cnt = ccnt[pp];
                const float* zcol = z_s + pp;
                float A = A_s[pp];
                float bb = 3.4e38f; int bk = KCODES;
                if (cnt <= MAXC) {
                    if (lane < cnt) {
                        int k = cand[pp][lane];
                        bb = df_dist(zcol, emb + (size_t)k * DDIM, A, en_s[k]);
                        bk = k;
                    }
                } else {
                    for (int k = lane; k < KCODES; k += 32) {
                        float dv = df_dist(zcol, emb + (size_t)k * DDIM, A, en_s[k]);
                        if (dv < bb || (dv == bb && k < bk)) { bb = dv; bk = k; }
                    }
                }
#pragma unroll
                for (int off = 16; off; off >>= 1) {
                    float ov = __shfl_xor_sync(0xffffffffu, bb, off);
                    int   ok = __shfl_xor_sync(0xffffffffu, bk, off);
                    if (ov < bb || (ov == bb && ok < bk)) { bb = ov; bk = ok; }
                }
                if (lane == 0 && pp < nhere) out[pl_s[pp]] = (float)bk;
            }
        }
    }
}

// ---------------------------------------------------------------------------
extern "C" void kernel_launch(void* const* d_in, const int* in_sizes, int n_in,
                              void* d_out, int out_size) {
    const float* z   = nullptr;
    const float* emb = nullptr;
    for (int i = 0; i < n_in; i++) {
        long s = (long)in_sizes[i];
        if (s == 16777216L || s == 67108864L)   z   = (const float*)d_in[i];
        else if (s == 262144L || s == 1048576L) emb = (const float*)d_in[i];
    }
    if (!z)   z   = (const float*)d_in[0];
    if (!emb) emb = (const float*)d_in[n_in > 1 ? 1 : 0];
    float* out = (float*)d_out;

    reset_kernel<<<1, 32>>>();
    enorm_kernel<<<32, 32>>>(emb);
    anorm_kernel<<<NPIX / 128, 128>>>(z);

    size_t smw = (size_t)SMEMW_FLOATS * sizeof(float);
    cudaFuncSetAttribute(vq5, cudaFuncAttributeMaxDynamicSharedMemorySize,
                         (int)smw);
    vq5<<<NPIX / BPW, THREADS, smw>>>(z, emb, out);
    fixup3<<<256, FTH>>>(z, emb, out);
}

// round 14
// speedup vs baseline: 1.6060x; 1.2214x over previous
#include <cuda_runtime.h>
#include <cstddef>

#define KCODES 1024
#define DDIM   256
#define NPIX   65536
#define THREADS 512
#define MARGIN  7.5e-5f
#define CAND_SLACK 2e-4f

// ---- main kernel geometry ----
#define BPW 128      // pixels per block
#define TKW 128      // codes per tile
#define DCW 64       // d per chunk
#define SE  132      // e_s row stride in floats (mult of 4 for LDS.128 align)
#define CHUNK_F (DCW * SE)               // 8448 floats per buffer

// smem: z (32768 f) | e 2 buffers (16896 f) | en (1024 f) | A (128 f)
#define ZW_OFF   0
#define E_OFF    32768
#define ENW_OFF  (32768 + 2 * CHUNK_F)   // 49664
#define AW_OFF   (ENW_OFF + 1024)
#define SMEMW_FLOATS (AW_OFF + 128)      // 50816 floats = 203,264 B

__device__ float g_enorm[KCODES];
__device__ float g_A[NPIX];
__device__ float g_bv[NPIX];
__device__ int   g_nflag;
__device__ int   g_flags[NPIX];

#define FMA2(a, x, y) \
    asm("fma.rn.f32x2 %0, %1, %2, %0;" : "+l"(a) : "l"(x), "l"(y))
#define DUP2(d, s) \
    asm("mov.b64 %0, {%1,%1};" : "=l"(d) : "f"(s))

// ---------------------------------------------------------------------------
// Emulated reference row sum-of-squares (proven exact R7-R13).
// ---------------------------------------------------------------------------
__device__ __forceinline__ float sumsq_emul(const float* x, long stride) {
    float S[8];
#pragma unroll
    for (int l = 0; l < 8; l++) S[l] = 0.f;
    for (int t = 0; t < DDIM / 8; t++) {
#pragma unroll
        for (int l = 0; l < 8; l++) {
            float v = x[(long)(8 * t + l) * stride];
            S[l] = __fadd_rn(S[l], __fmul_rn(v, v));
        }
    }
    float m0 = __fadd_rn(S[0], S[4]);
    float m1 = __fadd_rn(S[1], S[5]);
    float m2 = __fadd_rn(S[2], S[6]);
    float m3 = __fadd_rn(S[3], S[7]);
    return __fadd_rn(__fadd_rn(m0, m1), __fadd_rn(m2, m3));
}

__global__ void reset_kernel() { if (threadIdx.x == 0) g_nflag = 0; }

__global__ void enorm_kernel(const float* __restrict__ emb) {
    int c = blockIdx.x * blockDim.x + threadIdx.x;
    if (c < KCODES) g_enorm[c] = sumsq_emul(emb + (size_t)c * DDIM, 1);
}

__global__ void anorm_kernel(const float* __restrict__ z) {
    int p = blockIdx.x * blockDim.x + threadIdx.x;
    if (p < NPIX) {
        const float* zp = z + (size_t)(p >> 12) * (DDIM * 4096) + (p & 4095);
        g_A[p] = sumsq_emul(zp, 4096);
    }
}

// ---------------------------------------------------------------------------
// Main pass: 512 threads, 128 px/block, warp = 32 px x 32 codes,
// thread = 4 px x 8 codes. Accs packed as CODE-pairs (e loads u64 directly
// from float e_s), z duplicated via 4 movs. Conflict-free staging
// (warp writes 32 consecutive codes per STS). Double-buffered, DCW=64.
// ---------------------------------------------------------------------------
__global__ __launch_bounds__(THREADS, 1)
void vq6(const float* __restrict__ z, const float* __restrict__ emb,
         float* __restrict__ out) {
    extern __shared__ float smem[];
    float* z_s  = smem + ZW_OFF;
    float* e_s  = smem + E_OFF;
    float* en_s = smem + ENW_OFF;
    float* A_s  = smem + AW_OFF;

    const int tid  = threadIdx.x;
    const int lane = tid & 31;
    const int w    = tid >> 5;          // 16 warps
    const int pxg  = lane & 7;          // 8 px-groups
    const int cg   = lane >> 3;         // 4 code-groups
    const int band = w & 3;             // 4 px-bands of 32
    const int ccl  = w >> 2;            // 4 code-clusters of 32
    const int px0  = band * 32 + pxg * 4;   // this thread's 4 pixels
    const int cofs = ccl * 32 + cg * 8;     // 8 codes within tile

    const int n0 = blockIdx.x * BPW;
    const float* zbase = z + (size_t)(n0 >> 12) * (DDIM * 4096) + (n0 & 4095);

    // ---- z tile [256][128], coalesced ----
#pragma unroll
    for (int it = 0; it < 16; it++) {
        int idx = it * THREADS + tid;            // 8192 float4 slots
        int d = idx >> 5, c4 = (idx & 31) << 2;
        *(float4*)(z_s + d * BPW + c4) =
            *(const float4*)(zbase + (size_t)d * 4096 + c4);
    }
    for (int i = tid; i < KCODES; i += THREADS) en_s[i] = g_enorm[i];
    if (tid < BPW) A_s[tid] = g_A[n0 + tid];
    __syncthreads();

    float A4[4];
#pragma unroll
    for (int j = 0; j < 4; j++) A4[j] = A_s[px0 + j];

    float bv[4], sv[4]; int bi[4];
#pragma unroll
    for (int j = 0; j < 4; j++) { bv[j] = 3.4e38f; sv[j] = 3.4e38f; bi[j] = 0; }

    // staging identity: thread covers 16 d-rows of one code
    const int s_code  = tid & 127;      // warp -> 32 consecutive codes
    const int s_dbase = (tid >> 7) * 16;

    for (int k0 = 0; k0 < KCODES; k0 += TKW) {
        unsigned long long acc[4][4];   // 4 px x 4 code-pairs
#pragma unroll
        for (int i = 0; i < 4; i++)
#pragma unroll
            for (int c = 0; c < 4; c++) acc[i][c] = 0ull;

        const float* erow = emb + (size_t)(k0 + s_code) * DDIM + s_dbase;

        // prologue: load + store chunk 0 into buffer 0
        float4 st0, st1, st2, st3;
        st0 = *(const float4*)(erow + 0);
        st1 = *(const float4*)(erow + 4);
        st2 = *(const float4*)(erow + 8);
        st3 = *(const float4*)(erow + 12);
        {
            float* dst = e_s + s_dbase * SE + s_code;
            float f[16] = {st0.x, st0.y, st0.z, st0.w, st1.x, st1.y, st1.z, st1.w,
                           st2.x, st2.y, st2.z, st2.w, st3.x, st3.y, st3.z, st3.w};
#pragma unroll
            for (int j = 0; j < 16; j++) dst[j * SE] = f[j];
        }
        __syncthreads();

        for (int ch = 0; ch < DDIM / DCW; ch++) {
            if (ch < DDIM / DCW - 1) {           // prefetch next chunk
                const float* er = erow + (ch + 1) * DCW;
                st0 = *(const float4*)(er + 0);
                st1 = *(const float4*)(er + 4);
                st2 = *(const float4*)(er + 8);
                st3 = *(const float4*)(er + 12);
            }

            const float* eb = e_s + (ch & 1) * CHUNK_F + cofs;
            const float* zb = z_s + (size_t)(ch * DCW) * BPW + px0;
#pragma unroll 4
            for (int d = 0; d < DCW; d++) {
                float4 zf = *(const float4*)(zb + (size_t)d * BPW);
                ulonglong2 e01 = *(const ulonglong2*)(eb + (size_t)d * SE);
                ulonglong2 e23 = *(const ulonglong2*)(eb + (size_t)d * SE + 4);
                unsigned long long zd[4], ec[4] = {e01.x, e01.y, e23.x, e23.y};
                DUP2(zd[0], zf.x); DUP2(zd[1], zf.y);
                DUP2(zd[2], zf.z); DUP2(zd[3], zf.w);
#pragma unroll
                for (int i = 0; i < 4; i++)
#pragma unroll
                    for (int c = 0; c < 4; c++)
                        FMA2(acc[i][c], zd[i], ec[c]);
            }

            if (ch < DDIM / DCW - 1) {           // store prefetched chunk
                float* dst = e_s + ((ch + 1) & 1) * CHUNK_F
                                 + s_dbase * SE + s_code;
                float f[16] = {st0.x, st0.y, st0.z, st0.w, st1.x, st1.y, st1.z, st1.w,
                               st2.x, st2.y, st2.z, st2.w, st3.x, st3.y, st3.z, st3.w};
#pragma unroll
                for (int j = 0; j < 16; j++) dst[j * SE] = f[j];
            }
            __syncthreads();
        }

        // epilogue: acc[i][c] = codes (cofs+2c, cofs+2c+1) for pixel px0+i.
        // c ascending, lo before hi -> ascending k, strict '<' (first-index ties)
#pragma unroll
        for (int c = 0; c < 4; c++) {
            int klo = k0 + cofs + 2 * c;
            float enlo = en_s[klo], enhi = en_s[klo + 1];
#pragma unroll
            for (int i = 0; i < 4; i++) {
                float lo = __uint_as_float((unsigned)(acc[i][c] & 0xffffffffull));
                float hi = __uint_as_float((unsigned)(acc[i][c] >> 32));
                float dl = __fadd_rn(__fsub_rn(A4[i], __fmul_rn(2.0f, lo)), enlo);
                float dh = __fadd_rn(__fsub_rn(A4[i], __fmul_rn(2.0f, hi)), enhi);
                if (dl < bv[i]) { sv[i] = bv[i]; bv[i] = dl; bi[i] = klo; }
                else if (dl < sv[i]) sv[i] = dl;
                if (dh < bv[i]) { sv[i] = bv[i]; bv[i] = dh; bi[i] = klo + 1; }
                else if (dh < sv[i]) sv[i] = dh;
            }
        }
    }

    // ---- cross-thread merge: 16 contributors (ccl x cg) per pixel ----
    __syncthreads();
    float* rv = z_s;                     // reuse: [128][17]
    int*   ri = (int*)(z_s + 2176);
    float* rs = z_s + 4352;
    const int slot = ccl * 4 + cg;
#pragma unroll
    for (int j = 0; j < 4; j++) {
        int p = px0 + j;
        rv[p * 17 + slot] = bv[j];
        ri[p * 17 + slot] = bi[j];
        rs[p * 17 + slot] = sv[j];
    }
    __syncthreads();
    if (tid < BPW) {
        float b = rv[tid * 17]; int x0 = ri[tid * 17]; float s = rs[tid * 17];
#pragma unroll
        for (int t = 1; t < 16; t++) {
            float v = rv[tid * 17 + t]; int x = ri[tid * 17 + t];
            float s2 = rs[tid * 17 + t];
            if (v < b || (v == b && x < x0)) { s = fminf(b, s2); b = v; x0 = x; }
            else s = fminf(s, v);
        }
        out[n0 + tid]  = (float)x0;
        g_bv[n0 + tid] = b;
        if (__fsub_rn(s, b) < MARGIN) {
            int idx = atomicAdd(&g_nflag, 1);
            g_flags[idx] = n0 + tid;
        }
    }
}

// ---------------------------------------------------------------------------
// Fixup: fp32 screening (4 interleaved chains for MLP), then DF-exact dots
// on candidates only. Index tie-break makes collection order irrelevant.
// ---------------------------------------------------------------------------
#define FTH 256
#define FPX 16
#define MAXC 32

__device__ __forceinline__ float df_dist(const float* zcol, const float* er,
                                         float A, float en) {
    float hi = 0.f, lo = 0.f;
    for (int d = 0; d < DDIM; d++) {
        float x = zcol[d * FPX], y = er[d];
        float pm = __fmul_rn(x, y);
        float e1 = fmaf(x, y, -pm);
        float t  = __fadd_rn(hi, pm);
        float v  = __fsub_rn(t, hi);
        float e2 = __fadd_rn(__fsub_rn(hi, __fsub_rn(t, v)), __fsub_rn(pm, v));
        hi = t;
        lo = __fadd_rn(lo, __fadd_rn(e1, e2));
    }
    float M = __fadd_rn(hi, lo);
    return __fadd_rn(__fsub_rn(A, __fmul_rn(2.0f, M)), en);
}

__global__ __launch_bounds__(FTH)
void fixup3(const float* __restrict__ z, const float* __restrict__ emb,
            float* __restrict__ out) {
    __shared__ float z_s[DDIM * FPX];
    __shared__ float en_s[KCODES];
    __shared__ float A_s[FPX], bv_s[FPX];
    __shared__ int   pl_s[FPX], ccnt[FPX];
    __shared__ int   cand[FPX][MAXC];

    const int tid = threadIdx.x;
    for (int i = tid; i < KCODES; i += FTH) en_s[i] = g_enorm[i];

    for (int base = blockIdx.x * FPX; base < g_nflag; base += gridDim.x * FPX) {
        int nhere = g_nflag - base; if (nhere > FPX) nhere = FPX;
        __syncthreads();
        if (tid < FPX) {
            int p = g_flags[base + (tid < nhere ? tid : 0)];
            pl_s[tid] = p;
            A_s[tid]  = g_A[p];
            bv_s[tid] = g_bv[p];
            ccnt[tid] = 0;
        }
        __syncthreads();
        for (int i = tid; i < DDIM * FPX; i += FTH) {
            int d = i >> 4, q = i & 15;
            int p = pl_s[q];
            z_s[i] = z[(size_t)(p >> 12) * (DDIM * 4096)
                       + (size_t)d * 4096 + (p & 4095)];
        }
        __syncthreads();

        {   // screening: 4 interleaved code chains per j (MLP 4)
            int px = tid & 15, kg = tid >> 4;
            float A = A_s[px], thr = __fadd_rn(bv_s[px], CAND_SLACK);
            const float* zcol = z_s + px;
            for (int j = 0; j < 16; j++) {
                int kb = kg + 16 * j;
                const float* e0r = emb + (size_t)(kb      ) * DDIM;
                const float* e1r = emb + (size_t)(kb + 256) * DDIM;
                const float* e2r = emb + (size_t)(kb + 512) * DDIM;
                const float* e3r = emb + (size_t)(kb + 768) * DDIM;
                float a0 = 0.f, a1 = 0.f, a2 = 0.f, a3 = 0.f;
#pragma unroll 8
                for (int d = 0; d < DDIM; d++) {
                    float zv = zcol[d * FPX];
                    a0 = fmaf(zv, e0r[d], a0);
                    a1 = fmaf(zv, e1r[d], a1);
                    a2 = fmaf(zv, e2r[d], a2);
                    a3 = fmaf(zv, e3r[d], a3);
                }
                float dv[4] = {
                    __fadd_rn(__fsub_rn(A, __fmul_rn(2.0f, a0)), en_s[kb]),
                    __fadd_rn(__fsub_rn(A, __fmul_rn(2.0f, a1)), en_s[kb + 256]),
                    __fadd_rn(__fsub_rn(A, __fmul_rn(2.0f, a2)), en_s[kb + 512]),
                    __fadd_rn(__fsub_rn(A, __fmul_rn(2.0f, a3)), en_s[kb + 768])};
#pragma unroll
                for (int c = 0; c < 4; c++) {
                    if (dv[c] < thr) {
                        int s = atomicAdd(&ccnt[px], 1);
                        if (s < MAXC) cand[px][s] = kb + 256 * c;
                    }
                }
            }
        }
        __syncthreads();

        {   // DF phase: warp w handles px w, w+8
            int warp = tid >> 5, lane = tid & 31;
            for (int pp = warp; pp < FPX; pp += 8) {
                int cnt = ccnt[pp];
                const float* zcol = z_s + pp;
                float A = A_s[pp];
                float bb = 3.4e38f; int bk = KCODES;
                if (cnt <= MAXC) {
                    if (lane < cnt) {
                        int k = cand[pp][lane];
                        bb = df_dist(zcol, emb + (size_t)k * DDIM, A, en_s[k]);
                        bk = k;
                    }
                } else {
                    for (int k = lane; k < KCODES; k += 32) {
                        float dv = df_dist(zcol, emb + (size_t)k * DDIM, A, en_s[k]);
                        if (dv < bb || (dv == bb && k < bk)) { bb = dv; bk = k; }
                    }
                }
#pragma unroll
                for (int off = 16; off; off >>= 1) {
                    float ov = __shfl_xor_sync(0xffffffffu, bb, off);
                    int   ok = __shfl_xor_sync(0xffffffffu, bk, off);
                    if (ov < bb || (ov == bb && ok < bk)) { bb = ov; bk = ok; }
                }
                if (lane == 0 && pp < nhere) out[pl_s[pp]] = (float)bk;
            }
        }
    }
}

// ---------------------------------------------------------------------------
extern "C" void kernel_launch(void* const* d_in, const int* in_sizes, int n_in,
                              void* d_out, int out_size) {
    const float* z   = nullptr;
    const float* emb = nullptr;
    for (int i = 0; i < n_in; i++) {
        long s = (long)in_sizes[i];
        if (s == 16777216L || s == 67108864L)   z   = (const float*)d_in[i];
        else if (s == 262144L || s == 1048576L) emb = (const float*)d_in[i];
    }
    if (!z)   z   = (const float*)d_in[0];
    if (!emb) emb = (const float*)d_in[n_in > 1 ? 1 : 0];
    float* out = (float*)d_out;

    reset_kernel<<<1, 32>>>();
    enorm_kernel<<<32, 32>>>(emb);
    anorm_kernel<<<NPIX / 128, 128>>>(z);

    size_t smw = (size_t)SMEMW_FLOATS * sizeof(float);
    cudaFuncSetAttribute(vq6, cudaFuncAttributeMaxDynamicSharedMemorySize,
                         (int)smw);
    vq6<<<NPIX / BPW, THREADS, smw>>>(z, emb, out);
    fixup3<<<256, FTH>>>(z, emb, out);
}